// round 14
// baseline (speedup 1.0000x reference)
#include <cuda_runtime.h>
#include <cuda_bf16.h>
#include <cstdint>

typedef unsigned long long ull;

#define NBLK 128
#define NTHR 512

// ---- persistent device state (no allocation) ----
__device__ float g_hA[2][16384];
__device__ float g_cA[16384];
__device__ float g_h1[2][16384];
__device__ float g_c1[16384];
__device__ float g_h2[2][16384];
__device__ float g_c2[16384];
__device__ float g_ctx[16384];
__device__ float g_sc[16384];
__device__ float g_pmax[128];
__device__ float g_psum[128];
__device__ unsigned g_cnt;   // cumulative barrier arrivals
__device__ unsigned g_gen;   // cumulative released epochs

// ---- dynamic smem layout (float offsets) ----
#define WCELL   16384                 // [jj 16][k 1024], unpadded (16B aligned)
#define A_OFF   (3 * WCELL)           // 49152: two A buffers [2][32][128] XOR-swizzled
#define P_OFF   A_OFF                 // kh-partials [16][512] overlay both A buffers
#define SCR_OFF A_OFF                 // attention/final scratch overlays A
#define AROW    132                   // attention partial row stride
#define SMEM_FLOATS (A_OFF + 8192)
#define SMEM_BYTES  (SMEM_FLOATS * 4) // 229,376 B

__device__ __forceinline__ void ffma2(ull& d, ull a, ull b) {
    asm("fma.rn.f32x2 %0, %1, %2, %0;" : "+l"(d) : "l"(a), "l"(b));
}
__device__ __forceinline__ float2 ull2f2(ull v) {
    float2 r;
    asm("mov.b64 {%0, %1}, %2;" : "=f"(r.x), "=f"(r.y) : "l"(v));
    return r;
}

// Grid barrier: per-thread release fence, red-arrive (pipelined), CTA0 release.
// Cumulative epochs make it graph-replay safe (base read before first arrive).
// RELEASE correctness: every thread fences its OWN prior global stores before
// the entry __syncthreads; tid0's arrive is therefore ordered after all of
// them (fence -> syncthreads -> arrive). Consumers read mutable state with
// __ldcg (L2-coherent), so no acquire-side L1 staleness.
__device__ __forceinline__ void gbar(unsigned& ep, unsigned base) {
    __threadfence();
    __syncthreads();
    ep++;
    if (threadIdx.x == 0) {
        unsigned tgt = base + ep;
        unsigned one = 1u;
        asm volatile("red.global.add.u32 [%0], %1;" :: "l"(&g_cnt), "r"(one) : "memory");
        if (blockIdx.x == 0) {
            unsigned want = tgt * (unsigned)NBLK;
            unsigned v;
            do {
                asm volatile("ld.global.cg.u32 %0, [%1];" : "=r"(v) : "l"(&g_cnt) : "memory");
            } while ((int)(v - want) < 0);
            __threadfence();
            asm volatile("st.global.cg.u32 [%0], %1;" :: "l"(&g_gen), "r"(tgt) : "memory");
        } else {
            unsigned v;
            do {
                asm volatile("ld.global.cg.u32 %0, [%1];" : "=r"(v) : "l"(&g_gen) : "memory");
                if ((int)(v - tgt) >= 0) break;
                __nanosleep(20);
            } while (true);
        }
        __threadfence();
    }
    __syncthreads();
}

// One LSTM cell. z = [in ; hrec] @ [W ; R] + bias (this CTA's 16 gate cols),
// CTA owns u in [u0, u0+4). Weights resident in smem, layout [jj][k 0..1023].
// Map: warp = kh (16 k-slices, 8 k per 128-k chunk); lane = mg(8) | colg(4)<<3.
// Tile per thread: 4 cols x 4 rows. A double-buffered, XOR-swizzled.
__device__ void cell(const float* __restrict__ in0, long long instride,
                     const float* __restrict__ hrec,
                     float* __restrict__ c_st, float* __restrict__ h_out,
                     const float* __restrict__ bias,
                     int cellIdx, int u0, float* __restrict__ sm) {
    float* Wsm = sm + cellIdx * WCELL;
    float* A0  = sm + A_OFF;
    float* P   = sm + P_OFF;
    const int tid = threadIdx.x;
    const int am = tid >> 4, akq = tid & 15;     // staging decode
    const int lane = tid & 31, kh = tid >> 5;
    const int mg = lane & 7, colg = lane >> 3;
    const int m0 = mg << 2, jbase = colg << 2;
    const int sta = am * 128 + ((akq ^ (am >> 2)) << 2);  // swizzled staging addr

    float4 pf0, pf1;
    {   // fetch + stage chunk 0 (k 0..127, from in0) into buffer 0
        const float* src = in0 + (long long)am * instride + akq * 4;
        pf0 = __ldcg((const float4*)src);
        pf1 = __ldcg((const float4*)(src + 64));
    }
    *(float4*)(A0 + sta)      = pf0;
    *(float4*)(A0 + sta + 64) = pf1;
    __syncthreads();

    ull acc00 = 0, acc01 = 0, acc02 = 0, acc03 = 0;
    ull acc10 = 0, acc11 = 0, acc12 = 0, acc13 = 0;
    ull acc20 = 0, acc21 = 0, acc22 = 0, acc23 = 0;
    ull acc30 = 0, acc31 = 0, acc32 = 0, acc33 = 0;

    #pragma unroll 1
    for (int c = 0; c < 8; ++c) {
        if (c < 7) {
            const int cn = c + 1;
            const float* base = (cn < 4)
                ? (in0 + (long long)am * instride + cn * 128)
                : (hrec + am * 512 + (cn - 4) * 128);
            pf0 = __ldcg((const float4*)(base + akq * 4));
            pf1 = __ldcg((const float4*)(base + akq * 4 + 64));
        }
        const float* A_s = A0 + (c & 1) * 4096;
        const float* Wb = Wsm + jbase * 1024 + c * 128 + kh * 8;
        #pragma unroll
        for (int kq = 0; kq < 2; ++kq) {
            const int kc = kh * 2 + kq;
            ulonglong2 w0 = *(const ulonglong2*)(Wb            + kq * 4);
            ulonglong2 w1 = *(const ulonglong2*)(Wb + 1024     + kq * 4);
            ulonglong2 w2 = *(const ulonglong2*)(Wb + 2 * 1024 + kq * 4);
            ulonglong2 w3 = *(const ulonglong2*)(Wb + 3 * 1024 + kq * 4);
            const int sw = (kc ^ mg) << 2;
            ulonglong2 a0 = *(const ulonglong2*)(A_s + (m0    ) * 128 + sw);
            ulonglong2 a1 = *(const ulonglong2*)(A_s + (m0 + 1) * 128 + sw);
            ulonglong2 a2 = *(const ulonglong2*)(A_s + (m0 + 2) * 128 + sw);
            ulonglong2 a3 = *(const ulonglong2*)(A_s + (m0 + 3) * 128 + sw);
            // x-pass (k, k+1)
            ffma2(acc00, a0.x, w0.x); ffma2(acc01, a1.x, w0.x);
            ffma2(acc02, a2.x, w0.x); ffma2(acc03, a3.x, w0.x);
            ffma2(acc10, a0.x, w1.x); ffma2(acc11, a1.x, w1.x);
            ffma2(acc12, a2.x, w1.x); ffma2(acc13, a3.x, w1.x);
            ffma2(acc20, a0.x, w2.x); ffma2(acc21, a1.x, w2.x);
            ffma2(acc22, a2.x, w2.x); ffma2(acc23, a3.x, w2.x);
            ffma2(acc30, a0.x, w3.x); ffma2(acc31, a1.x, w3.x);
            ffma2(acc32, a2.x, w3.x); ffma2(acc33, a3.x, w3.x);
            // y-pass (k+2, k+3)
            ffma2(acc00, a0.y, w0.y); ffma2(acc01, a1.y, w0.y);
            ffma2(acc02, a2.y, w0.y); ffma2(acc03, a3.y, w0.y);
            ffma2(acc10, a0.y, w1.y); ffma2(acc11, a1.y, w1.y);
            ffma2(acc12, a2.y, w1.y); ffma2(acc13, a3.y, w1.y);
            ffma2(acc20, a0.y, w2.y); ffma2(acc21, a1.y, w2.y);
            ffma2(acc22, a2.y, w2.y); ffma2(acc23, a3.y, w2.y);
            ffma2(acc30, a0.y, w3.y); ffma2(acc31, a1.y, w3.y);
            ffma2(acc32, a2.y, w3.y); ffma2(acc33, a3.y, w3.y);
        }
        if (c < 7) {   // stage next chunk into the idle buffer
            float* An = A0 + ((c + 1) & 1) * 4096;
            *(float4*)(An + sta)      = pf0;
            *(float4*)(An + sta + 64) = pf1;
        }
        __syncthreads();
    }

    // horizontal combine -> 16 scalars, store this warp's partial slice
    {
        float2 t;
        float4 vv0, vv1, vv2, vv3;
        t = ull2f2(acc00); vv0.x = t.x + t.y;
        t = ull2f2(acc01); vv0.y = t.x + t.y;
        t = ull2f2(acc02); vv0.z = t.x + t.y;
        t = ull2f2(acc03); vv0.w = t.x + t.y;
        t = ull2f2(acc10); vv1.x = t.x + t.y;
        t = ull2f2(acc11); vv1.y = t.x + t.y;
        t = ull2f2(acc12); vv1.z = t.x + t.y;
        t = ull2f2(acc13); vv1.w = t.x + t.y;
        t = ull2f2(acc20); vv2.x = t.x + t.y;
        t = ull2f2(acc21); vv2.y = t.x + t.y;
        t = ull2f2(acc22); vv2.z = t.x + t.y;
        t = ull2f2(acc23); vv2.w = t.x + t.y;
        t = ull2f2(acc30); vv3.x = t.x + t.y;
        t = ull2f2(acc31); vv3.y = t.x + t.y;
        t = ull2f2(acc32); vv3.z = t.x + t.y;
        t = ull2f2(acc33); vv3.w = t.x + t.y;
        float* pd = P + kh * 512;
        *(float4*)(pd + (jbase    ) * 32 + m0) = vv0;
        *(float4*)(pd + (jbase + 1) * 32 + m0) = vv1;
        *(float4*)(pd + (jbase + 2) * 32 + m0) = vv2;
        *(float4*)(pd + (jbase + 3) * 32 + m0) = vv3;
    }
    __syncthreads();

    if (tid < 128) {
        int m = tid & 31, q = tid >> 5;
        int u = u0 + q;
        float z0 = __ldg(bias + u);
        float z1 = __ldg(bias + u + 512);
        float z2 = __ldg(bias + u + 1024);
        float z3 = __ldg(bias + u + 1536);
        #pragma unroll
        for (int k2 = 0; k2 < 16; ++k2) {
            const float* pr = P + k2 * 512 + m;
            z0 += pr[(q     ) * 32];
            z1 += pr[(q + 4 ) * 32];
            z2 += pr[(q + 8 ) * 32];
            z3 += pr[(q + 12) * 32];
        }
        float ig = 1.f / (1.f + expf(-z0));
        float fg = 1.f / (1.f + expf(-z1));
        float gg = tanhf(z2);
        float og = 1.f / (1.f + expf(-z3));
        float cv = fg * __ldcg(c_st + m * 512 + u) + ig * gg;
        c_st[m * 512 + u]  = cv;
        h_out[m * 512 + u] = og * tanhf(cv);
    }
    __syncthreads();
}

__global__ void __launch_bounds__(NTHR, 1)
spk(const float* __restrict__ x,  const float* __restrict__ y,
    const float* __restrict__ Wa, const float* __restrict__ Ra, const float* __restrict__ ba,
    const float* __restrict__ W1, const float* __restrict__ R1, const float* __restrict__ b1,
    const float* __restrict__ W2, const float* __restrict__ R2, const float* __restrict__ b2,
    const float* __restrict__ Wd, const float* __restrict__ bd,
    float* __restrict__ out) {
    extern __shared__ float sm[];
    const int blk = blockIdx.x, tid = threadIdx.x;
    const int lane = tid & 31, warp = tid >> 5;
    const int u0 = blk * 4;

    // barrier epoch base (read by every CTA before its first arrival)
    unsigned gbase;
    asm volatile("ld.global.cg.u32 %0, [%1];" : "=r"(gbase) : "l"(&g_gen) : "memory");
    unsigned ep = 0;

    // ---- one-time persistent weight load: sm[c][jj][k] = stacked [W;R] col slice ----
    {
        const float* Ws[3] = {Wa, W1, W2};
        const float* Rs[3] = {Ra, R1, R2};
        #pragma unroll
        for (int c = 0; c < 3; ++c) {
            const float* Wc = Ws[c];
            const float* Rc = Rs[c];
            for (int i = tid; i < 16384; i += NTHR) {
                int j = i >> 10, k = i & 1023;
                int col = u0 + (j & 3) + ((j >> 2) << 9);
                float v = (k < 512) ? __ldg(Wc + (size_t)k * 2048 + col)
                                    : __ldg(Rc + (size_t)(k - 512) * 2048 + col);
                sm[c * WCELL + j * 1024 + k] = v;
            }
        }
    }

    // ---- zero initial states (globals persist across graph replays) ----
    {
        float* bufs[9] = {g_hA[0], g_hA[1], g_cA, g_h1[0], g_h1[1], g_c1,
                          g_h2[0], g_h2[1], g_c2};
        int base = blk * NTHR + tid;
        #pragma unroll
        for (int a = 0; a < 9; ++a)
            for (int i = base; i < 16384; i += NBLK * NTHR) bufs[a][i] = 0.f;
    }
    gbar(ep, gbase);

    for (int t = 0; t < 130; ++t) {
        // ---------- stage 1: software-pipelined cells ----------
        if (t < 128)
            cell(y + (size_t)t * 512, 128LL * 512, g_hA[(t + 1) & 1],
                 g_cA, g_hA[t & 1], ba, 0, u0, sm);
        if (t >= 1 && t <= 128)
            cell(g_ctx, 512LL, g_h1[(t + 1) & 1],
                 g_c1, g_h1[t & 1], b1, 1, u0, sm);
        if (t >= 2)
            cell(g_h1[(t + 1) & 1], 512LL, g_h2[(t + 1) & 1],
                 g_c2, g_h2[t & 1], b2, 2, u0, sm);
        gbar(ep, gbase);

        // ---------- phase S: scores + partial softmax stats ----------
        if (t < 128) {
            int b = blk >> 2, sq = blk & 3;
            float* hs   = sm + SCR_OFF;     // 512
            float* sc   = hs + 512;         // 128
            float* wred = sc + 128;         // 4
            const float* hA = g_hA[t & 1] + b * 512;
            hs[tid] = __ldcg(hA + tid);
            __syncthreads();
            const float4* hr = (const float4*)hs;
            float4 hv[4];
            #pragma unroll
            for (int i2 = 0; i2 < 4; ++i2) hv[i2] = hr[lane + 32 * i2];
            #pragma unroll 1
            for (int si = 0; si < 8; si += 2) {
                int sl0 = warp + si * 16;
                const float4* xr0 = (const float4*)(x + ((size_t)(b * 512 + sq * 128 + sl0)) * 512);
                const float4* xr1 = xr0 + 16 * 128;
                float4 x0[4], x1[4];
                #pragma unroll
                for (int i2 = 0; i2 < 4; ++i2) {
                    x0[i2] = __ldg(xr0 + lane + 32 * i2);
                    x1[i2] = __ldg(xr1 + lane + 32 * i2);
                }
                float a0 = 0.f, a1 = 0.f;
                #pragma unroll
                for (int i2 = 0; i2 < 4; ++i2) {
                    a0 += x0[i2].x * hv[i2].x + x0[i2].y * hv[i2].y
                        + x0[i2].z * hv[i2].z + x0[i2].w * hv[i2].w;
                    a1 += x1[i2].x * hv[i2].x + x1[i2].y * hv[i2].y
                        + x1[i2].z * hv[i2].z + x1[i2].w * hv[i2].w;
                }
                #pragma unroll
                for (int o = 16; o; o >>= 1) {
                    a0 += __shfl_xor_sync(0xffffffffu, a0, o);
                    a1 += __shfl_xor_sync(0xffffffffu, a1, o);
                }
                if (lane == 0) { sc[sl0] = a0; sc[sl0 + 16] = a1; }
            }
            __syncthreads();
            if (tid < 128) {
                float v = sc[tid];
                #pragma unroll
                for (int o = 16; o; o >>= 1) v = fmaxf(v, __shfl_xor_sync(0xffffffffu, v, o));
                if (lane == 0) wred[warp] = v;
            }
            __syncthreads();
            if (tid < 128) {
                float M = fmaxf(fmaxf(wred[0], wred[1]), fmaxf(wred[2], wred[3]));
                float e = expf(sc[tid] - M);
                #pragma unroll
                for (int o = 16; o; o >>= 1) e += __shfl_xor_sync(0xffffffffu, e, o);
                g_sc[b * 512 + sq * 128 + tid] = sc[tid];
                if (lane == 0) wred[warp] = e;
                __syncwarp();
                if (tid == 0) {
                    g_pmax[b * 4 + sq] = M;
                    g_psum[b * 4 + sq] = wred[0] + wred[1] + wred[2] + wred[3];
                }
            }
        }
        gbar(ep, gbase);

        // ---------- phase X: global softmax, ctx slice, residual ----------
        if (t < 128) {
            int b = blk >> 2, uq = blk & 3;
            float pm[4], ps[4], M = -1e30f;
            #pragma unroll
            for (int q = 0; q < 4; ++q) {
                pm[q] = __ldcg(g_pmax + b * 4 + q);
                ps[q] = __ldcg(g_psum + b * 4 + q);
                M = fmaxf(M, pm[q]);
            }
            float S = 0.f;
            #pragma unroll
            for (int q = 0; q < 4; ++q) S += ps[q] * expf(pm[q] - M);
            float invS = 1.f / S;
            float* ws   = sm + SCR_OFF;       // 512 weights
            float* part = ws + 512;           // [16][132]
            ws[tid] = expf(__ldcg(g_sc + b * 512 + tid) - M) * invS;
            __syncthreads();
            int ug = tid & 31, ss = tid >> 5;
            int ub = uq * 128 + ug * 4;
            const float4* xc = (const float4*)(x + ((size_t)(b * 512) + ss * 32) * 512 + ub);
            const float* wp = ws + ss * 32;
            float4 acc = make_float4(0.f, 0.f, 0.f, 0.f);
            #pragma unroll 8
            for (int s2 = 0; s2 < 32; ++s2) {
                float4 v = __ldg(xc + (size_t)s2 * 128);
                float w = wp[s2];
                acc.x += w * v.x; acc.y += w * v.y;
                acc.z += w * v.z; acc.w += w * v.w;
            }
            *(float4*)(part + ss * AROW + ug * 4) = acc;
            __syncthreads();
            if (tid < 128) {
                float ctxv = 0.f;
                #pragma unroll
                for (int s = 0; s < 16; ++s) ctxv += part[s * AROW + tid];
                int idx = b * 512 + uq * 128 + tid;
                g_ctx[idx] = ctxv;
                g_hA[t & 1][idx] = __ldcg(&g_hA[t & 1][idx]) + ctxv;
                g_cA[idx]        = __ldcg(&g_cA[idx]) + ctxv;
            }
        }
        gbar(ep, gbase);
    }

    // ---------- final dense 512->46 + softmax (hT = g_h2[1]) ----------
    if (blk < 32) {
        int b = blk;
        float* hs = sm + SCR_OFF;
        float* lg = hs + 512;
        hs[tid] = __ldcg(g_h2[1] + b * 512 + tid);
        __syncthreads();
        for (int v = warp; v < 46; v += 16) {
            float acc = 0.f;
            #pragma unroll 4
            for (int k = lane; k < 512; k += 32)
                acc += hs[k] * __ldg(Wd + (size_t)k * 46 + v);
            #pragma unroll
            for (int o = 16; o; o >>= 1) acc += __shfl_xor_sync(0xffffffffu, acc, o);
            if (lane == 0) lg[v] = acc + __ldg(bd + v);
        }
        __syncthreads();
        if (tid == 0) {
            float M = lg[0];
            for (int v = 1; v < 46; ++v) M = fmaxf(M, lg[v]);
            float S = 0.f;
            for (int v = 0; v < 46; ++v) { float e = expf(lg[v] - M); lg[v] = e; S += e; }
            float inv = 1.f / S;
            for (int v = 0; v < 46; ++v) out[b * 46 + v] = lg[v] * inv;
        }
    }
}

extern "C" void kernel_launch(void* const* d_in, const int* in_sizes, int n_in,
                              void* d_out, int out_size) {
    const float* x  = (const float*)d_in[0];
    const float* y  = (const float*)d_in[1];
    const float* Wa = (const float*)d_in[2];
    const float* Ra = (const float*)d_in[3];
    const float* ba = (const float*)d_in[4];
    const float* W1 = (const float*)d_in[5];
    const float* R1 = (const float*)d_in[6];
    const float* b1 = (const float*)d_in[7];
    const float* W2 = (const float*)d_in[8];
    const float* R2 = (const float*)d_in[9];
    const float* b2 = (const float*)d_in[10];
    const float* Wd = (const float*)d_in[11];
    const float* bd = (const float*)d_in[12];
    cudaFuncSetAttribute(spk, cudaFuncAttributeMaxDynamicSharedMemorySize, SMEM_BYTES);
    spk<<<NBLK, NTHR, SMEM_BYTES>>>(x, y, Wa, Ra, ba, W1, R1, b1, W2, R2, b2,
                                    Wd, bd, (float*)d_out);
}